// round 1
// baseline (speedup 1.0000x reference)
#include <cuda_runtime.h>
#include <math.h>

// Problem constants
#define Bb   2
#define Ll   1024
#define Tt   2048        // Bb*Ll tokens
#define DIN  512
#define DM   1024
#define NLr  4
#define EE   2048
#define NN   16
#define RR   64

// ---------------- scratch (device globals; no runtime allocation) ----------
__device__ float g_h   [Tt * DM];            // residual stream
__device__ float g_hn  [Tt * DM];            // layernorm output
__device__ float g_xz  [Tt * 2 * EE];        // inproj output (xm | zg)
__device__ float g_xm  [Tt * EE];            // conv+silu output
__device__ float g_xdbl[Tt * 96];            // xproj output (dt_r | B | C)
__device__ float g_dt  [Tt * EE];            // softplus(dt)
__device__ float g_y   [Tt * EE];            // scan output (gated)
__device__ float g_A   [NLr * EE * NN];      // -exp(A_log)

// ---------------------------------------------------------------------------
// Main SGEMM: C[M,N] = A[M,K] * W[N,K]^T (+bias) (+= if BETA)
// 128x128 block tile, 8x8 thread tile, BK=8, double-buffered smem.
// Requires M%128==0, N%128==0, K%8==0.
// ---------------------------------------------------------------------------
template<int BETA, int BIAS>
__global__ __launch_bounds__(256, 2)
void sgemm128(const float* __restrict__ A, const float* __restrict__ W,
              const float* __restrict__ bias, float* __restrict__ C,
              int M, int N, int K)
{
    __shared__ float As[2][8][128];
    __shared__ float Bs[2][8][128];
    const int tid = threadIdx.x;
    const int bm = blockIdx.y * 128;
    const int bn = blockIdx.x * 128;
    const int lr = tid >> 1;            // 0..127
    const int lc = (tid & 1) << 2;      // 0 or 4
    const float* Ag = A + (size_t)(bm + lr) * K + lc;
    const float* Wg = W + (size_t)(bn + lr) * K + lc;

    float4 aR = *(const float4*)Ag;
    float4 bR = *(const float4*)Wg;
    As[0][lc + 0][lr] = aR.x; As[0][lc + 1][lr] = aR.y;
    As[0][lc + 2][lr] = aR.z; As[0][lc + 3][lr] = aR.w;
    Bs[0][lc + 0][lr] = bR.x; Bs[0][lc + 1][lr] = bR.y;
    Bs[0][lc + 2][lr] = bR.z; Bs[0][lc + 3][lr] = bR.w;
    __syncthreads();

    const int tx = tid & 15;
    const int ty = tid >> 4;
    float acc[8][8];
#pragma unroll
    for (int i = 0; i < 8; i++)
#pragma unroll
        for (int j = 0; j < 8; j++) acc[i][j] = 0.f;

    const int nt = K >> 3;
    for (int kt = 0; kt < nt; kt++) {
        const int buf = kt & 1;
        if (kt + 1 < nt) {
            aR = *(const float4*)(Ag + (size_t)(kt + 1) * 8);
            bR = *(const float4*)(Wg + (size_t)(kt + 1) * 8);
        }
#pragma unroll
        for (int k = 0; k < 8; k++) {
            float a[8], b[8];
            *(float4*)(a)     = *(const float4*)&As[buf][k][ty * 8];
            *(float4*)(a + 4) = *(const float4*)&As[buf][k][ty * 8 + 4];
            *(float4*)(b)     = *(const float4*)&Bs[buf][k][tx * 8];
            *(float4*)(b + 4) = *(const float4*)&Bs[buf][k][tx * 8 + 4];
#pragma unroll
            for (int i = 0; i < 8; i++)
#pragma unroll
                for (int j = 0; j < 8; j++)
                    acc[i][j] = fmaf(a[i], b[j], acc[i][j]);
        }
        if (kt + 1 < nt) {
            const int nb = buf ^ 1;
            As[nb][lc + 0][lr] = aR.x; As[nb][lc + 1][lr] = aR.y;
            As[nb][lc + 2][lr] = aR.z; As[nb][lc + 3][lr] = aR.w;
            Bs[nb][lc + 0][lr] = bR.x; Bs[nb][lc + 1][lr] = bR.y;
            Bs[nb][lc + 2][lr] = bR.z; Bs[nb][lc + 3][lr] = bR.w;
        }
        __syncthreads();
    }

#pragma unroll
    for (int i = 0; i < 8; i++) {
        const int row = bm + ty * 8 + i;
        float* Cr = C + (size_t)row * N + bn + tx * 8;
#pragma unroll
        for (int j = 0; j < 8; j++) {
            float v = acc[i][j];
            if (BIAS) v += bias[bn + tx * 8 + j];
            if (BETA) Cr[j] += v; else Cr[j] = v;
        }
    }
}

// ---------------------------------------------------------------------------
// LayerNorm: one block per token row (D = DM = 1024), 256 threads x float4.
// ---------------------------------------------------------------------------
__global__ void ln_kernel(const float* __restrict__ x, const float* __restrict__ w,
                          const float* __restrict__ b, float* __restrict__ o)
{
    __shared__ float s1[8], s2[8];
    const int row = blockIdx.x;
    const int tid = threadIdx.x;
    const float4 v = ((const float4*)(x + (size_t)row * DM))[tid];
    float s  = v.x + v.y + v.z + v.w;
    float ss = v.x * v.x + v.y * v.y + v.z * v.z + v.w * v.w;
#pragma unroll
    for (int off = 16; off; off >>= 1) {
        s  += __shfl_xor_sync(0xffffffffu, s,  off);
        ss += __shfl_xor_sync(0xffffffffu, ss, off);
    }
    if ((tid & 31) == 0) { s1[tid >> 5] = s; s2[tid >> 5] = ss; }
    __syncthreads();
    float ts = 0.f, tss = 0.f;
#pragma unroll
    for (int i = 0; i < 8; i++) { ts += s1[i]; tss += s2[i]; }
    const float mean = ts * (1.f / DM);
    const float var  = tss * (1.f / DM) - mean * mean;
    const float rstd = rsqrtf(var + 1e-5f);
    const float4 wv = ((const float4*)w)[tid];
    const float4 bv = ((const float4*)b)[tid];
    float4 r;
    r.x = (v.x - mean) * rstd * wv.x + bv.x;
    r.y = (v.y - mean) * rstd * wv.y + bv.y;
    r.z = (v.z - mean) * rstd * wv.z + bv.z;
    r.w = (v.w - mean) * rstd * wv.w + bv.w;
    ((float4*)(o + (size_t)row * DM))[tid] = r;
}

// ---------------------------------------------------------------------------
// Depthwise causal conv (K=4) + SiLU, reading xm-half of g_xz, writing g_xm.
// ---------------------------------------------------------------------------
__global__ void conv_kernel(const float* __restrict__ cw, const float* __restrict__ cb)
{
    const int idx = blockIdx.x * 256 + threadIdx.x;      // over Tt*EE
    const int e  = idx & (EE - 1);
    const int bt = idx >> 11;                            // b*Ll + t
    const int t  = bt & (Ll - 1);
    float acc = cb[e];
    const float* base = g_xz + (size_t)bt * (2 * EE) + e;
#pragma unroll
    for (int k = 0; k < 4; k++) {
        const int tt = t - 3 + k;
        if (tt >= 0) acc += cw[e * 4 + k] * base[(size_t)(k - 3) * (2 * EE)];
    }
    g_xm[idx] = acc / (1.f + __expf(-acc));
}

// ---------------------------------------------------------------------------
// xproj GEMM: g_xdbl[T,96] = g_xm[T,2048] * W[96,2048]^T
// BM=32 rows, full 96 cols, BK=32; thread tile 2x6; 256 threads.
// ---------------------------------------------------------------------------
__global__ __launch_bounds__(256)
void xproj_kernel(const float* __restrict__ W)
{
    __shared__ float Ast[32][32];   // [k][m]
    __shared__ float Bst[32][96];   // [k][n]
    const int tid = threadIdx.x;
    const int bm = blockIdx.x * 32;
    const int lm = tid >> 3;            // 0..31
    const int k4 = (tid & 7) << 2;      // 0..28
    const int ty = tid >> 4;            // 0..15
    const int tx = tid & 15;            // 0..15
    float acc[2][6];
#pragma unroll
    for (int i = 0; i < 2; i++)
#pragma unroll
        for (int j = 0; j < 6; j++) acc[i][j] = 0.f;

    for (int k0 = 0; k0 < EE; k0 += 32) {
        float4 av = *(const float4*)(g_xm + (size_t)(bm + lm) * EE + k0 + k4);
        Ast[k4 + 0][lm] = av.x; Ast[k4 + 1][lm] = av.y;
        Ast[k4 + 2][lm] = av.z; Ast[k4 + 3][lm] = av.w;
#pragma unroll
        for (int r = 0; r < 3; r++) {
            const int n = lm + 32 * r;
            float4 wv = *(const float4*)(W + (size_t)n * EE + k0 + k4);
            Bst[k4 + 0][n] = wv.x; Bst[k4 + 1][n] = wv.y;
            Bst[k4 + 2][n] = wv.z; Bst[k4 + 3][n] = wv.w;
        }
        __syncthreads();
#pragma unroll
        for (int k = 0; k < 32; k++) {
            const float a0 = Ast[k][2 * ty];
            const float a1 = Ast[k][2 * ty + 1];
#pragma unroll
            for (int j = 0; j < 6; j++) {
                const float bvv = Bst[k][6 * tx + j];
                acc[0][j] = fmaf(a0, bvv, acc[0][j]);
                acc[1][j] = fmaf(a1, bvv, acc[1][j]);
            }
        }
        __syncthreads();
    }
#pragma unroll
    for (int i = 0; i < 2; i++)
#pragma unroll
        for (int j = 0; j < 6; j++)
            g_xdbl[(size_t)(bm + 2 * ty + i) * 96 + 6 * tx + j] = acc[i][j];
}

// ---------------------------------------------------------------------------
// dtproj GEMM + softplus: g_dt[T,2048] = softplus(xdbl[:, :64] * W[2048,64]^T + b)
// BM=16 tokens x BN=128 channels, K=64 in one shot.
// ---------------------------------------------------------------------------
__global__ __launch_bounds__(256)
void dt_kernel(const float* __restrict__ W, const float* __restrict__ db)
{
    __shared__ float Xs[16][64];
    __shared__ float Wt[64][132];   // [k][n], row stride 132 (16B-aligned, low conflict)
    const int tid = threadIdx.x;
    const int bm = blockIdx.y * 16;
    const int bn = blockIdx.x * 128;
    {
        const int m  = tid >> 4;
        const int k4 = (tid & 15) << 2;
        *(float4*)&Xs[m][k4] = *(const float4*)(g_xdbl + (size_t)(bm + m) * 96 + k4);
    }
#pragma unroll
    for (int r = 0; r < 8; r++) {
        const int idx = tid + 256 * r;
        const int n  = idx >> 4;
        const int k4 = (idx & 15) << 2;
        float4 v = *(const float4*)(W + (size_t)(bn + n) * 64 + k4);
        Wt[k4 + 0][n] = v.x; Wt[k4 + 1][n] = v.y;
        Wt[k4 + 2][n] = v.z; Wt[k4 + 3][n] = v.w;
    }
    __syncthreads();

    const int nb = (tid & 31) << 2;   // 0..124
    const int m0 = tid >> 5;          // 0..7
    float acc[2][4];
#pragma unroll
    for (int i = 0; i < 2; i++)
#pragma unroll
        for (int j = 0; j < 4; j++) acc[i][j] = 0.f;
#pragma unroll
    for (int k = 0; k < 64; k++) {
        const float4 w = *(const float4*)&Wt[k][nb];
        const float x0 = Xs[m0][k];
        const float x1 = Xs[m0 + 8][k];
        acc[0][0] = fmaf(x0, w.x, acc[0][0]); acc[0][1] = fmaf(x0, w.y, acc[0][1]);
        acc[0][2] = fmaf(x0, w.z, acc[0][2]); acc[0][3] = fmaf(x0, w.w, acc[0][3]);
        acc[1][0] = fmaf(x1, w.x, acc[1][0]); acc[1][1] = fmaf(x1, w.y, acc[1][1]);
        acc[1][2] = fmaf(x1, w.z, acc[1][2]); acc[1][3] = fmaf(x1, w.w, acc[1][3]);
    }
#pragma unroll
    for (int i = 0; i < 2; i++) {
        const int row = bm + m0 + 8 * i;
#pragma unroll
        for (int j = 0; j < 4; j++) {
            float v = acc[i][j] + db[bn + nb + j];
            v = (v > 20.f) ? v : log1pf(expf(v));
            g_dt[(size_t)row * EE + bn + nb + j] = v;
        }
    }
}

// ---------------------------------------------------------------------------
// Selective scan, fused epilogue: y = (scan + u*D) * silu(zg).
// Block = 128 threads = 8 channels x 16 state lanes; sequential over L.
// ---------------------------------------------------------------------------
__global__ __launch_bounds__(128)
void scan_kernel(int layer, const float* __restrict__ Dl)
{
    const int b = blockIdx.y;
    const int e = blockIdx.x * 8 + (threadIdx.x >> 4);
    const int n = threadIdx.x & 15;
    const float Av = g_A[(size_t)layer * EE * NN + e * NN + n];
    const float Dv = Dl[e];
    const float* dtp = g_dt + (size_t)b * Ll * EE + e;
    const float* up  = g_xm + (size_t)b * Ll * EE + e;
    const float* xd  = g_xdbl + (size_t)b * Ll * 96;
    const float* zgp = g_xz + (size_t)b * Ll * (2 * EE) + EE + e;
    float*       yp  = g_y  + (size_t)b * Ll * EE + e;

    float h = 0.f;
    float dt0 = dtp[0], u0 = up[0];
    float Bv0 = xd[64 + n], Cv0 = xd[80 + n];
    float zg0 = zgp[0];

    for (int t = 0; t < Ll; t++) {
        float dt1 = 0.f, u1 = 0.f, Bv1 = 0.f, Cv1 = 0.f, zg1 = 0.f;
        if (t + 1 < Ll) {
            dt1 = dtp[(size_t)(t + 1) * EE];
            u1  = up [(size_t)(t + 1) * EE];
            Bv1 = xd[(t + 1) * 96 + 64 + n];
            Cv1 = xd[(t + 1) * 96 + 80 + n];
            zg1 = zgp[(size_t)(t + 1) * (2 * EE)];
        }
        const float dA = __expf(dt0 * Av);
        h = fmaf(dA, h, dt0 * u0 * Bv0);
        float p = h * Cv0;
        p += __shfl_xor_sync(0xffffffffu, p, 8);
        p += __shfl_xor_sync(0xffffffffu, p, 4);
        p += __shfl_xor_sync(0xffffffffu, p, 2);
        p += __shfl_xor_sync(0xffffffffu, p, 1);
        if (n == 0) {
            const float sil = zg0 / (1.f + __expf(-zg0));
            yp[(size_t)t * EE] = (p + u0 * Dv) * sil;
        }
        dt0 = dt1; u0 = u1; Bv0 = Bv1; Cv0 = Cv1; zg0 = zg1;
    }
}

// ---------------------------------------------------------------------------
__global__ void prep_A(const float* __restrict__ A_log)
{
    const int i = blockIdx.x * 256 + threadIdx.x;
    g_A[i] = -expf(A_log[i]);
}

// ---------------------------------------------------------------------------
extern "C" void kernel_launch(void* const* d_in, const int* in_sizes, int n_in,
                              void* d_out, int out_size)
{
    const float* x         = (const float*)d_in[0];
    // d_in[1] (z) is unused by the reference
    const float* ip_w      = (const float*)d_in[2];
    const float* ip_b      = (const float*)d_in[3];
    const float* ln_w      = (const float*)d_in[4];
    const float* ln_b      = (const float*)d_in[5];
    const float* inproj_w  = (const float*)d_in[6];
    const float* conv_w    = (const float*)d_in[7];
    const float* conv_b    = (const float*)d_in[8];
    const float* xproj_w   = (const float*)d_in[9];
    const float* dtproj_w  = (const float*)d_in[10];
    const float* dtproj_b  = (const float*)d_in[11];
    const float* A_log     = (const float*)d_in[12];
    const float* Dp        = (const float*)d_in[13];
    const float* outproj_w = (const float*)d_in[14];
    const float* fnorm_w   = (const float*)d_in[15];
    const float* fnorm_b   = (const float*)d_in[16];
    const float* op_w      = (const float*)d_in[17];
    const float* op_b      = (const float*)d_in[18];
    float* out = (float*)d_out;

    float *p_h, *p_hn, *p_xz, *p_y;
    cudaGetSymbolAddress((void**)&p_h,  g_h);
    cudaGetSymbolAddress((void**)&p_hn, g_hn);
    cudaGetSymbolAddress((void**)&p_xz, g_xz);
    cudaGetSymbolAddress((void**)&p_y,  g_y);

    prep_A<<<(NLr * EE * NN) / 256, 256>>>(A_log);

    // h = x @ ip_w^T + ip_b
    sgemm128<0, 1><<<dim3(DM / 128, Tt / 128), 256>>>(x, ip_w, ip_b, p_h, Tt, DM, DIN);

    for (int l = 0; l < NLr; l++) {
        ln_kernel<<<Tt, 256>>>(p_h, ln_w + (size_t)l * DM, ln_b + (size_t)l * DM, p_hn);

        // xz = hn @ inproj_w^T   [T, 4096]
        sgemm128<0, 0><<<dim3((2 * EE) / 128, Tt / 128), 256>>>(
            p_hn, inproj_w + (size_t)l * 2 * EE * DM, nullptr, p_xz, Tt, 2 * EE, DM);

        // xm = silu(causal depthwise conv)
        conv_kernel<<<(Tt * EE) / 256, 256>>>(conv_w + (size_t)l * EE * 4,
                                              conv_b + (size_t)l * EE);

        // x_dbl = xm @ xproj_w^T   [T, 96]
        xproj_kernel<<<Tt / 32, 256>>>(xproj_w + (size_t)l * 96 * EE);

        // dt = softplus(x_dbl[:, :64] @ dtproj_w^T + b)   [T, 2048]
        dt_kernel<<<dim3(EE / 128, Tt / 16), 256>>>(dtproj_w + (size_t)l * EE * RR,
                                                    dtproj_b + (size_t)l * EE);

        // selective scan + gating  -> y [T, 2048]
        scan_kernel<<<dim3(EE / 8, Bb), 128>>>(l, Dp + (size_t)l * EE);

        // h += y @ outproj_w^T
        sgemm128<1, 0><<<dim3(DM / 128, Tt / 128), 256>>>(
            p_y, outproj_w + (size_t)l * DM * EE, nullptr, p_h, Tt, DM, EE);
    }

    ln_kernel<<<Tt, 256>>>(p_h, fnorm_w, fnorm_b, p_hn);

    // out = hn @ op_w^T + op_b   [T, 512]
    sgemm128<0, 1><<<dim3(DIN / 128, Tt / 128), 256>>>(p_hn, op_w, op_b, out, Tt, DIN, DM);
}

// round 2
// speedup vs baseline: 2.2886x; 2.2886x over previous
#include <cuda_runtime.h>
#include <math.h>
#include <stdint.h>

// Problem constants
#define Bb   2
#define Ll   1024
#define Tt   2048        // Bb*Ll tokens
#define DIN  512
#define DM   1024
#define NLr  4
#define EE   2048
#define NN   16
#define RR   64

// ---------------- scratch (device globals; no runtime allocation) ----------
__device__ float g_h   [Tt * DM];            // residual stream
__device__ float g_hn  [Tt * DM];            // layernorm output
__device__ float g_xz  [Tt * 2 * EE];        // inproj output (xm | zg)
__device__ float g_xm  [Tt * EE];            // conv+silu output
__device__ float g_xdbl[Tt * 96];            // xproj output (dt_r | B | C)
__device__ float g_dt  [Tt * EE];            // softplus(dt)
__device__ float g_y   [Tt * EE];            // scan output (gated)
__device__ float g_A   [NLr * EE * NN];      // -exp(A_log)

// ---------------------------------------------------------------------------
// tf32 helpers
// ---------------------------------------------------------------------------
__device__ __forceinline__ uint32_t f2tf(float x) {
    uint32_t r;
    asm("cvt.rna.tf32.f32 %0, %1;" : "=r"(r) : "f"(x));
    return r;
}

__device__ __forceinline__ void mma8(float& d0, float& d1, float& d2, float& d3,
                                     uint32_t a0, uint32_t a1, uint32_t a2, uint32_t a3,
                                     uint32_t b0, uint32_t b1) {
    asm volatile(
        "mma.sync.aligned.m16n8k8.row.col.f32.tf32.tf32.f32 "
        "{%0,%1,%2,%3}, {%4,%5,%6,%7}, {%8,%9}, {%0,%1,%2,%3};"
        : "+f"(d0), "+f"(d1), "+f"(d2), "+f"(d3)
        : "r"(a0), "r"(a1), "r"(a2), "r"(a3), "r"(b0), "r"(b1));
}

// ---------------------------------------------------------------------------
// TF32 tensor-core GEMM: C[M,N] = A[M,K] * W[N,K]^T (+bias) (+= if BETA)
// Block tile: (WMW*64) x (WNW*32), warp tile 64x32 (4x4 of m16n8k8), BK=16,
// double-buffered smem with padded [row][20] layout (conflict-free frags).
// Requires M % BM == 0, N % BN == 0, K % 16 == 0.
// ---------------------------------------------------------------------------
template<int WMW, int WNW, int BETA, int BIAS>
__global__ __launch_bounds__(WMW * WNW * 32, 2)
void tgemm(const float* __restrict__ A, const float* __restrict__ W,
           const float* __restrict__ bias, float* __restrict__ C,
           int M, int N, int K)
{
    constexpr int NT  = WMW * WNW * 32;
    constexpr int BM  = WMW * 64;
    constexpr int BN  = WNW * 32;
    constexpr int AIT = (BM * 4 + NT - 1) / NT;   // float4 loads per thread (A)
    constexpr int BIT = (BN * 4 + NT - 1) / NT;   // float4 loads per thread (B)

    __shared__ uint32_t As[2][BM][20];
    __shared__ uint32_t Bs[2][BN][20];

    const int tid  = threadIdx.x;
    const int bm   = blockIdx.y * BM;
    const int bn   = blockIdx.x * BN;
    const int wid  = tid >> 5;
    const int lane = tid & 31;
    const int wm   = wid % WMW;
    const int wn   = wid / WMW;
    const int l4   = lane >> 2;
    const int lr   = lane & 3;

    const float* Ag = A + (size_t)bm * K;
    const float* Wg = W + (size_t)bn * K;

    float acc[4][4][4];
#pragma unroll
    for (int i = 0; i < 4; i++)
#pragma unroll
        for (int j = 0; j < 4; j++)
#pragma unroll
            for (int k = 0; k < 4; k++) acc[i][j][k] = 0.f;

    // Prologue: load tile kt=0 into stage 0
#pragma unroll
    for (int i = 0; i < AIT; i++) {
        const int f = tid + i * NT;
        if (f < BM * 4) {
            const int row = f >> 2, c = (f & 3) << 2;
            const float4 v = *(const float4*)(Ag + (size_t)row * K + c);
            uint4 u; u.x = f2tf(v.x); u.y = f2tf(v.y); u.z = f2tf(v.z); u.w = f2tf(v.w);
            *(uint4*)&As[0][row][c] = u;
        }
    }
#pragma unroll
    for (int i = 0; i < BIT; i++) {
        const int f = tid + i * NT;
        if (f < BN * 4) {
            const int row = f >> 2, c = (f & 3) << 2;
            const float4 v = *(const float4*)(Wg + (size_t)row * K + c);
            uint4 u; u.x = f2tf(v.x); u.y = f2tf(v.y); u.z = f2tf(v.z); u.w = f2tf(v.w);
            *(uint4*)&Bs[0][row][c] = u;
        }
    }
    __syncthreads();

    const int nt = K >> 4;
    int cur = 0;
    for (int kt = 0; kt < nt; kt++) {
        float4 pA[AIT], pB[BIT];
        const bool pf = (kt + 1) < nt;
        if (pf) {
            const float* Ak = Ag + (size_t)(kt + 1) * 16;
            const float* Wk = Wg + (size_t)(kt + 1) * 16;
#pragma unroll
            for (int i = 0; i < AIT; i++) {
                const int f = tid + i * NT;
                if (f < BM * 4)
                    pA[i] = *(const float4*)(Ak + (size_t)(f >> 2) * K + ((f & 3) << 2));
            }
#pragma unroll
            for (int i = 0; i < BIT; i++) {
                const int f = tid + i * NT;
                if (f < BN * 4)
                    pB[i] = *(const float4*)(Wk + (size_t)(f >> 2) * K + ((f & 3) << 2));
            }
        }

        const uint32_t (*Ac)[20] = As[cur];
        const uint32_t (*Bc)[20] = Bs[cur];
#pragma unroll
        for (int ks = 0; ks < 2; ks++) {
            const int kc = ks * 8 + lr;
            uint32_t af[4][4], bf[4][2];
#pragma unroll
            for (int mt = 0; mt < 4; mt++) {
                const int rA = wm * 64 + mt * 16 + l4;
                af[mt][0] = Ac[rA][kc];
                af[mt][1] = Ac[rA + 8][kc];
                af[mt][2] = Ac[rA][kc + 4];
                af[mt][3] = Ac[rA + 8][kc + 4];
            }
#pragma unroll
            for (int ntt = 0; ntt < 4; ntt++) {
                const int rB = wn * 32 + ntt * 8 + l4;
                bf[ntt][0] = Bc[rB][kc];
                bf[ntt][1] = Bc[rB][kc + 4];
            }
#pragma unroll
            for (int mt = 0; mt < 4; mt++)
#pragma unroll
                for (int ntt = 0; ntt < 4; ntt++)
                    mma8(acc[mt][ntt][0], acc[mt][ntt][1], acc[mt][ntt][2], acc[mt][ntt][3],
                         af[mt][0], af[mt][1], af[mt][2], af[mt][3],
                         bf[ntt][0], bf[ntt][1]);
        }

        if (pf) {
            const int nb = cur ^ 1;
#pragma unroll
            for (int i = 0; i < AIT; i++) {
                const int f = tid + i * NT;
                if (f < BM * 4) {
                    const int row = f >> 2, c = (f & 3) << 2;
                    uint4 u; u.x = f2tf(pA[i].x); u.y = f2tf(pA[i].y);
                    u.z = f2tf(pA[i].z); u.w = f2tf(pA[i].w);
                    *(uint4*)&As[nb][row][c] = u;
                }
            }
#pragma unroll
            for (int i = 0; i < BIT; i++) {
                const int f = tid + i * NT;
                if (f < BN * 4) {
                    const int row = f >> 2, c = (f & 3) << 2;
                    uint4 u; u.x = f2tf(pB[i].x); u.y = f2tf(pB[i].y);
                    u.z = f2tf(pB[i].z); u.w = f2tf(pB[i].w);
                    *(uint4*)&Bs[nb][row][c] = u;
                }
            }
        }
        __syncthreads();
        cur ^= 1;
    }

    // Epilogue
#pragma unroll
    for (int mt = 0; mt < 4; mt++) {
        const int r0 = bm + wm * 64 + mt * 16 + l4;
#pragma unroll
        for (int ntt = 0; ntt < 4; ntt++) {
            const int c0 = bn + wn * 32 + ntt * 8 + lr * 2;
            float* p0 = C + (size_t)r0 * N + c0;
            float* p1 = p0 + (size_t)8 * N;
            float v0 = acc[mt][ntt][0], v1 = acc[mt][ntt][1];
            float v2 = acc[mt][ntt][2], v3 = acc[mt][ntt][3];
            if (BIAS) {
                const float b0 = bias[c0], b1 = bias[c0 + 1];
                v0 += b0; v1 += b1; v2 += b0; v3 += b1;
            }
            if (BETA) {
                const float2 o0 = *(const float2*)p0;
                const float2 o1 = *(const float2*)p1;
                v0 += o0.x; v1 += o0.y; v2 += o1.x; v3 += o1.y;
            }
            *(float2*)p0 = make_float2(v0, v1);
            *(float2*)p1 = make_float2(v2, v3);
        }
    }
}

// ---------------------------------------------------------------------------
// FP32 SGEMM (kept for the first/last projections to bound end-to-end error)
// ---------------------------------------------------------------------------
template<int BETA, int BIAS>
__global__ __launch_bounds__(256, 2)
void sgemm128(const float* __restrict__ A, const float* __restrict__ W,
              const float* __restrict__ bias, float* __restrict__ C,
              int M, int N, int K)
{
    __shared__ float As[2][8][128];
    __shared__ float Bs[2][8][128];
    const int tid = threadIdx.x;
    const int bm = blockIdx.y * 128;
    const int bn = blockIdx.x * 128;
    const int lr = tid >> 1;
    const int lc = (tid & 1) << 2;
    const float* Ag = A + (size_t)(bm + lr) * K + lc;
    const float* Wg = W + (size_t)(bn + lr) * K + lc;

    float4 aR = *(const float4*)Ag;
    float4 bR = *(const float4*)Wg;
    As[0][lc + 0][lr] = aR.x; As[0][lc + 1][lr] = aR.y;
    As[0][lc + 2][lr] = aR.z; As[0][lc + 3][lr] = aR.w;
    Bs[0][lc + 0][lr] = bR.x; Bs[0][lc + 1][lr] = bR.y;
    Bs[0][lc + 2][lr] = bR.z; Bs[0][lc + 3][lr] = bR.w;
    __syncthreads();

    const int tx = tid & 15;
    const int ty = tid >> 4;
    float acc[8][8];
#pragma unroll
    for (int i = 0; i < 8; i++)
#pragma unroll
        for (int j = 0; j < 8; j++) acc[i][j] = 0.f;

    const int nt = K >> 3;
    for (int kt = 0; kt < nt; kt++) {
        const int buf = kt & 1;
        if (kt + 1 < nt) {
            aR = *(const float4*)(Ag + (size_t)(kt + 1) * 8);
            bR = *(const float4*)(Wg + (size_t)(kt + 1) * 8);
        }
#pragma unroll
        for (int k = 0; k < 8; k++) {
            float a[8], b[8];
            *(float4*)(a)     = *(const float4*)&As[buf][k][ty * 8];
            *(float4*)(a + 4) = *(const float4*)&As[buf][k][ty * 8 + 4];
            *(float4*)(b)     = *(const float4*)&Bs[buf][k][tx * 8];
            *(float4*)(b + 4) = *(const float4*)&Bs[buf][k][tx * 8 + 4];
#pragma unroll
            for (int i = 0; i < 8; i++)
#pragma unroll
                for (int j = 0; j < 8; j++)
                    acc[i][j] = fmaf(a[i], b[j], acc[i][j]);
        }
        if (kt + 1 < nt) {
            const int nb = buf ^ 1;
            As[nb][lc + 0][lr] = aR.x; As[nb][lc + 1][lr] = aR.y;
            As[nb][lc + 2][lr] = aR.z; As[nb][lc + 3][lr] = aR.w;
            Bs[nb][lc + 0][lr] = bR.x; Bs[nb][lc + 1][lr] = bR.y;
            Bs[nb][lc + 2][lr] = bR.z; Bs[nb][lc + 3][lr] = bR.w;
        }
        __syncthreads();
    }

#pragma unroll
    for (int i = 0; i < 8; i++) {
        const int row = bm + ty * 8 + i;
        float* Cr = C + (size_t)row * N + bn + tx * 8;
#pragma unroll
        for (int j = 0; j < 8; j++) {
            float v = acc[i][j];
            if (BIAS) v += bias[bn + tx * 8 + j];
            if (BETA) Cr[j] += v; else Cr[j] = v;
        }
    }
}

// ---------------------------------------------------------------------------
// LayerNorm: one block per token row (D = DM = 1024), 256 threads x float4.
// ---------------------------------------------------------------------------
__global__ void ln_kernel(const float* __restrict__ x, const float* __restrict__ w,
                          const float* __restrict__ b, float* __restrict__ o)
{
    __shared__ float s1[8], s2[8];
    const int row = blockIdx.x;
    const int tid = threadIdx.x;
    const float4 v = ((const float4*)(x + (size_t)row * DM))[tid];
    float s  = v.x + v.y + v.z + v.w;
    float ss = v.x * v.x + v.y * v.y + v.z * v.z + v.w * v.w;
#pragma unroll
    for (int off = 16; off; off >>= 1) {
        s  += __shfl_xor_sync(0xffffffffu, s,  off);
        ss += __shfl_xor_sync(0xffffffffu, ss, off);
    }
    if ((tid & 31) == 0) { s1[tid >> 5] = s; s2[tid >> 5] = ss; }
    __syncthreads();
    float ts = 0.f, tss = 0.f;
#pragma unroll
    for (int i = 0; i < 8; i++) { ts += s1[i]; tss += s2[i]; }
    const float mean = ts * (1.f / DM);
    const float var  = tss * (1.f / DM) - mean * mean;
    const float rstd = rsqrtf(var + 1e-5f);
    const float4 wv = ((const float4*)w)[tid];
    const float4 bv = ((const float4*)b)[tid];
    float4 r;
    r.x = (v.x - mean) * rstd * wv.x + bv.x;
    r.y = (v.y - mean) * rstd * wv.y + bv.y;
    r.z = (v.z - mean) * rstd * wv.z + bv.z;
    r.w = (v.w - mean) * rstd * wv.w + bv.w;
    ((float4*)(o + (size_t)row * DM))[tid] = r;
}

// ---------------------------------------------------------------------------
// Depthwise causal conv (K=4) + SiLU, reading xm-half of g_xz, writing g_xm.
// ---------------------------------------------------------------------------
__global__ void conv_kernel(const float* __restrict__ cw, const float* __restrict__ cb)
{
    const int idx = blockIdx.x * 256 + threadIdx.x;      // over Tt*EE
    const int e  = idx & (EE - 1);
    const int bt = idx >> 11;                            // b*Ll + t
    const int t  = bt & (Ll - 1);
    float acc = cb[e];
    const float* base = g_xz + (size_t)bt * (2 * EE) + e;
#pragma unroll
    for (int k = 0; k < 4; k++) {
        const int tt = t - 3 + k;
        if (tt >= 0) acc += cw[e * 4 + k] * base[(size_t)(k - 3) * (2 * EE)];
    }
    g_xm[idx] = acc / (1.f + __expf(-acc));
}

// ---------------------------------------------------------------------------
// dtproj GEMM + softplus: g_dt[T,2048] = softplus(xdbl[:, :64] * W[2048,64]^T + b)
// ---------------------------------------------------------------------------
__global__ __launch_bounds__(256)
void dt_kernel(const float* __restrict__ W, const float* __restrict__ db)
{
    __shared__ float Xs[16][64];
    __shared__ float Wt[64][132];
    const int tid = threadIdx.x;
    const int bm = blockIdx.y * 16;
    const int bn = blockIdx.x * 128;
    {
        const int m  = tid >> 4;
        const int k4 = (tid & 15) << 2;
        *(float4*)&Xs[m][k4] = *(const float4*)(g_xdbl + (size_t)(bm + m) * 96 + k4);
    }
#pragma unroll
    for (int r = 0; r < 8; r++) {
        const int idx = tid + 256 * r;
        const int n  = idx >> 4;
        const int k4 = (idx & 15) << 2;
        float4 v = *(const float4*)(W + (size_t)(bn + n) * 64 + k4);
        Wt[k4 + 0][n] = v.x; Wt[k4 + 1][n] = v.y;
        Wt[k4 + 2][n] = v.z; Wt[k4 + 3][n] = v.w;
    }
    __syncthreads();

    const int nb = (tid & 31) << 2;
    const int m0 = tid >> 5;
    float acc[2][4];
#pragma unroll
    for (int i = 0; i < 2; i++)
#pragma unroll
        for (int j = 0; j < 4; j++) acc[i][j] = 0.f;
#pragma unroll
    for (int k = 0; k < 64; k++) {
        const float4 w = *(const float4*)&Wt[k][nb];
        const float x0 = Xs[m0][k];
        const float x1 = Xs[m0 + 8][k];
        acc[0][0] = fmaf(x0, w.x, acc[0][0]); acc[0][1] = fmaf(x0, w.y, acc[0][1]);
        acc[0][2] = fmaf(x0, w.z, acc[0][2]); acc[0][3] = fmaf(x0, w.w, acc[0][3]);
        acc[1][0] = fmaf(x1, w.x, acc[1][0]); acc[1][1] = fmaf(x1, w.y, acc[1][1]);
        acc[1][2] = fmaf(x1, w.z, acc[1][2]); acc[1][3] = fmaf(x1, w.w, acc[1][3]);
    }
#pragma unroll
    for (int i = 0; i < 2; i++) {
        const int row = bm + m0 + 8 * i;
#pragma unroll
        for (int j = 0; j < 4; j++) {
            float v = acc[i][j] + db[bn + nb + j];
            v = (v > 20.f) ? v : log1pf(expf(v));
            g_dt[(size_t)row * EE + bn + nb + j] = v;
        }
    }
}

// ---------------------------------------------------------------------------
// Selective scan, fused epilogue: y = (scan + u*D) * silu(zg).
// ---------------------------------------------------------------------------
__global__ __launch_bounds__(128)
void scan_kernel(int layer, const float* __restrict__ Dl)
{
    const int b = blockIdx.y;
    const int e = blockIdx.x * 8 + (threadIdx.x >> 4);
    const int n = threadIdx.x & 15;
    const float Av = g_A[(size_t)layer * EE * NN + e * NN + n];
    const float Dv = Dl[e];
    const float* dtp = g_dt + (size_t)b * Ll * EE + e;
    const float* up  = g_xm + (size_t)b * Ll * EE + e;
    const float* xd  = g_xdbl + (size_t)b * Ll * 96;
    const float* zgp = g_xz + (size_t)b * Ll * (2 * EE) + EE + e;
    float*       yp  = g_y  + (size_t)b * Ll * EE + e;

    float h = 0.f;
    float dt0 = dtp[0], u0 = up[0];
    float Bv0 = xd[64 + n], Cv0 = xd[80 + n];
    float zg0 = zgp[0];

    for (int t = 0; t < Ll; t++) {
        float dt1 = 0.f, u1 = 0.f, Bv1 = 0.f, Cv1 = 0.f, zg1 = 0.f;
        if (t + 1 < Ll) {
            dt1 = dtp[(size_t)(t + 1) * EE];
            u1  = up [(size_t)(t + 1) * EE];
            Bv1 = xd[(t + 1) * 96 + 64 + n];
            Cv1 = xd[(t + 1) * 96 + 80 + n];
            zg1 = zgp[(size_t)(t + 1) * (2 * EE)];
        }
        const float dA = __expf(dt0 * Av);
        h = fmaf(dA, h, dt0 * u0 * Bv0);
        float p = h * Cv0;
        p += __shfl_xor_sync(0xffffffffu, p, 8);
        p += __shfl_xor_sync(0xffffffffu, p, 4);
        p += __shfl_xor_sync(0xffffffffu, p, 2);
        p += __shfl_xor_sync(0xffffffffu, p, 1);
        if (n == 0) {
            const float sil = zg0 / (1.f + __expf(-zg0));
            yp[(size_t)t * EE] = (p + u0 * Dv) * sil;
        }
        dt0 = dt1; u0 = u1; Bv0 = Bv1; Cv0 = Cv1; zg0 = zg1;
    }
}

// ---------------------------------------------------------------------------
__global__ void prep_A(const float* __restrict__ A_log)
{
    const int i = blockIdx.x * 256 + threadIdx.x;
    g_A[i] = -expf(A_log[i]);
}

// ---------------------------------------------------------------------------
extern "C" void kernel_launch(void* const* d_in, const int* in_sizes, int n_in,
                              void* d_out, int out_size)
{
    const float* x         = (const float*)d_in[0];
    const float* ip_w      = (const float*)d_in[2];
    const float* ip_b      = (const float*)d_in[3];
    const float* ln_w      = (const float*)d_in[4];
    const float* ln_b      = (const float*)d_in[5];
    const float* inproj_w  = (const float*)d_in[6];
    const float* conv_w    = (const float*)d_in[7];
    const float* conv_b    = (const float*)d_in[8];
    const float* xproj_w   = (const float*)d_in[9];
    const float* dtproj_w  = (const float*)d_in[10];
    const float* dtproj_b  = (const float*)d_in[11];
    const float* A_log     = (const float*)d_in[12];
    const float* Dp        = (const float*)d_in[13];
    const float* outproj_w = (const float*)d_in[14];
    const float* fnorm_w   = (const float*)d_in[15];
    const float* fnorm_b   = (const float*)d_in[16];
    const float* op_w      = (const float*)d_in[17];
    const float* op_b      = (const float*)d_in[18];
    float* out = (float*)d_out;

    float *p_h, *p_hn, *p_xz, *p_xm, *p_xdbl, *p_y;
    cudaGetSymbolAddress((void**)&p_h,    g_h);
    cudaGetSymbolAddress((void**)&p_hn,   g_hn);
    cudaGetSymbolAddress((void**)&p_xz,   g_xz);
    cudaGetSymbolAddress((void**)&p_xm,   g_xm);
    cudaGetSymbolAddress((void**)&p_xdbl, g_xdbl);
    cudaGetSymbolAddress((void**)&p_y,    g_y);

    prep_A<<<(NLr * EE * NN) / 256, 256>>>(A_log);

    // h = x @ ip_w^T + ip_b  (fp32)
    sgemm128<0, 1><<<dim3(DM / 128, Tt / 128), 256>>>(x, ip_w, ip_b, p_h, Tt, DM, DIN);

    for (int l = 0; l < NLr; l++) {
        ln_kernel<<<Tt, 256>>>(p_h, ln_w + (size_t)l * DM, ln_b + (size_t)l * DM, p_hn);

        // xz = hn @ inproj_w^T   [T, 4096]  (tf32 tensor)
        tgemm<2, 4, 0, 0><<<dim3((2 * EE) / 128, Tt / 128), 256>>>(
            p_hn, inproj_w + (size_t)l * 2 * EE * DM, nullptr, p_xz, Tt, 2 * EE, DM);

        // xm = silu(causal depthwise conv)
        conv_kernel<<<(Tt * EE) / 256, 256>>>(conv_w + (size_t)l * EE * 4,
                                              conv_b + (size_t)l * EE);

        // x_dbl = xm @ xproj_w^T   [T, 96]  (tf32 tensor, BN=96)
        tgemm<2, 3, 0, 0><<<dim3(1, Tt / 128), 192>>>(
            p_xm, xproj_w + (size_t)l * 96 * EE, nullptr, p_xdbl, Tt, 96, EE);

        // dt = softplus(x_dbl[:, :64] @ dtproj_w^T + b)   [T, 2048]
        dt_kernel<<<dim3(EE / 128, Tt / 16), 256>>>(dtproj_w + (size_t)l * EE * RR,
                                                    dtproj_b + (size_t)l * EE);

        // selective scan + gating  -> y [T, 2048]
        scan_kernel<<<dim3(EE / 8, Bb), 128>>>(l, Dp + (size_t)l * EE);

        // h += y @ outproj_w^T  (tf32 tensor)
        tgemm<2, 4, 1, 0><<<dim3(DM / 128, Tt / 128), 256>>>(
            p_y, outproj_w + (size_t)l * DM * EE, nullptr, p_h, Tt, DM, EE);
    }

    ln_kernel<<<Tt, 256>>>(p_h, fnorm_w, fnorm_b, p_hn);

    // out = hn @ op_w^T + op_b   [T, 512]  (fp32)
    sgemm128<0, 1><<<dim3(DIN / 128, Tt / 128), 256>>>(p_hn, op_w, op_b, out, Tt, DIN, DM);
}

// round 3
// speedup vs baseline: 3.4053x; 1.4879x over previous
#include <cuda_runtime.h>
#include <math.h>
#include <stdint.h>

// Problem constants
#define Bb   2
#define Ll   1024
#define Tt   2048        // Bb*Ll tokens
#define DIN  512
#define DM   1024
#define NLr  4
#define EE   2048
#define NN   16
#define RR   64

// ---------------- scratch (device globals; no runtime allocation) ----------
__device__ float g_h   [Tt * DM];            // residual stream
__device__ float g_hn  [Tt * DM];            // layernorm output
__device__ float g_xz  [Tt * 2 * EE];        // inproj output (xm | zg)
__device__ float g_xm  [Tt * EE];            // conv+silu output
__device__ float g_xdbl[Tt * 96];            // xproj output (dt_r | B | C)
__device__ float g_dt  [Tt * EE];            // softplus(dt)
__device__ float g_y   [Tt * EE];            // scan output (gated)
__device__ float g_A   [NLr * EE * NN];      // -exp(A_log)

// ---------------------------------------------------------------------------
// helpers
// ---------------------------------------------------------------------------
__device__ __forceinline__ uint32_t f2tf(float x) {
    uint32_t r;
    asm("cvt.rna.tf32.f32 %0, %1;" : "=r"(r) : "f"(x));
    return r;
}

__device__ __forceinline__ void mma8(float& d0, float& d1, float& d2, float& d3,
                                     uint32_t a0, uint32_t a1, uint32_t a2, uint32_t a3,
                                     uint32_t b0, uint32_t b1) {
    asm volatile(
        "mma.sync.aligned.m16n8k8.row.col.f32.tf32.tf32.f32 "
        "{%0,%1,%2,%3}, {%4,%5,%6,%7}, {%8,%9}, {%0,%1,%2,%3};"
        : "+f"(d0), "+f"(d1), "+f"(d2), "+f"(d3)
        : "r"(a0), "r"(a1), "r"(a2), "r"(a3), "r"(b0), "r"(b1));
}

__device__ __forceinline__ void cp16(void* dst, const void* src) {
    uint32_t d = (uint32_t)__cvta_generic_to_shared(dst);
    asm volatile("cp.async.cg.shared.global [%0], [%1], 16;" :: "r"(d), "l"(src));
}
__device__ __forceinline__ void cp4(void* dst, const void* src) {
    uint32_t d = (uint32_t)__cvta_generic_to_shared(dst);
    asm volatile("cp.async.ca.shared.global [%0], [%1], 4;" :: "r"(d), "l"(src));
}
__device__ __forceinline__ void cpcommit() {
    asm volatile("cp.async.commit_group;");
}
template<int NG> __device__ __forceinline__ void cpwait() {
    asm volatile("cp.async.wait_group %0;" :: "n"(NG));
}

// ---------------------------------------------------------------------------
// TF32 tensor-core GEMM: C[M,N] = A[M,K] * W[N,K]^T (+bias) (+= if BETA)
// Block tile: (WMW*64) x (WNW*32), warp tile 64x32 (4x4 of m16n8k8), BK=16.
// 2-stage cp.async pipeline, raw fp32 in smem, cvt.rna at fragment load.
// Requires M % BM == 0, N % BN == 0, K % 16 == 0, nt >= 2.
// ---------------------------------------------------------------------------
template<int WMW, int WNW, int BETA, int BIAS>
__global__ __launch_bounds__(WMW * WNW * 32, 2)
void tgemm(const float* __restrict__ A, const float* __restrict__ W,
           const float* __restrict__ bias, float* __restrict__ C,
           int M, int N, int K)
{
    constexpr int NT  = WMW * WNW * 32;
    constexpr int BM  = WMW * 64;
    constexpr int BN  = WNW * 32;
    constexpr int AIT = (BM * 4 + NT - 1) / NT;   // 16B chunks per thread (A)
    constexpr int BIT = (BN * 4 + NT - 1) / NT;   // 16B chunks per thread (B)

    __shared__ float As[2][BM][20];
    __shared__ float Bs[2][BN][20];

    const int tid  = threadIdx.x;
    const int bm   = blockIdx.y * BM;
    const int bn   = blockIdx.x * BN;
    const int wid  = tid >> 5;
    const int lane = tid & 31;
    const int wm   = wid % WMW;
    const int wn   = wid / WMW;
    const int l4   = lane >> 2;
    const int lr   = lane & 3;

    const float* Ag = A + (size_t)bm * K;
    const float* Wg = W + (size_t)bn * K;

    float acc[4][4][4];
#pragma unroll
    for (int i = 0; i < 4; i++)
#pragma unroll
        for (int j = 0; j < 4; j++)
#pragma unroll
            for (int k = 0; k < 4; k++) acc[i][j][k] = 0.f;

    auto load_stage = [&](int st, int kt) {
        const float* Ak = Ag + (size_t)kt * 16;
        const float* Wk = Wg + (size_t)kt * 16;
#pragma unroll
        for (int i = 0; i < AIT; i++) {
            const int f = tid + i * NT;
            if (f < BM * 4) {
                const int row = f >> 2, c = (f & 3) << 2;
                cp16(&As[st][row][c], Ak + (size_t)row * K + c);
            }
        }
#pragma unroll
        for (int i = 0; i < BIT; i++) {
            const int f = tid + i * NT;
            if (f < BN * 4) {
                const int row = f >> 2, c = (f & 3) << 2;
                cp16(&Bs[st][row][c], Wk + (size_t)row * K + c);
            }
        }
        cpcommit();
    };

    load_stage(0, 0);

    const int nt = K >> 4;
    for (int kt = 0; kt < nt; kt++) {
        cpwait<0>();
        __syncthreads();
        if (kt + 1 < nt) load_stage((kt + 1) & 1, kt + 1);

        const float (*Ac)[20] = As[kt & 1];
        const float (*Bc)[20] = Bs[kt & 1];
#pragma unroll
        for (int ks = 0; ks < 2; ks++) {
            const int kc = ks * 8 + lr;
            uint32_t af[4][4], bf[4][2];
#pragma unroll
            for (int mt = 0; mt < 4; mt++) {
                const int rA = wm * 64 + mt * 16 + l4;
                af[mt][0] = f2tf(Ac[rA][kc]);
                af[mt][1] = f2tf(Ac[rA + 8][kc]);
                af[mt][2] = f2tf(Ac[rA][kc + 4]);
                af[mt][3] = f2tf(Ac[rA + 8][kc + 4]);
            }
#pragma unroll
            for (int ntt = 0; ntt < 4; ntt++) {
                const int rB = wn * 32 + ntt * 8 + l4;
                bf[ntt][0] = f2tf(Bc[rB][kc]);
                bf[ntt][1] = f2tf(Bc[rB][kc + 4]);
            }
#pragma unroll
            for (int mt = 0; mt < 4; mt++)
#pragma unroll
                for (int ntt = 0; ntt < 4; ntt++)
                    mma8(acc[mt][ntt][0], acc[mt][ntt][1], acc[mt][ntt][2], acc[mt][ntt][3],
                         af[mt][0], af[mt][1], af[mt][2], af[mt][3],
                         bf[ntt][0], bf[ntt][1]);
        }
        __syncthreads();
    }

    // Epilogue
#pragma unroll
    for (int mt = 0; mt < 4; mt++) {
        const int r0 = bm + wm * 64 + mt * 16 + l4;
#pragma unroll
        for (int ntt = 0; ntt < 4; ntt++) {
            const int c0 = bn + wn * 32 + ntt * 8 + lr * 2;
            float* p0 = C + (size_t)r0 * N + c0;
            float* p1 = p0 + (size_t)8 * N;
            float v0 = acc[mt][ntt][0], v1 = acc[mt][ntt][1];
            float v2 = acc[mt][ntt][2], v3 = acc[mt][ntt][3];
            if (BIAS) {
                const float b0 = bias[c0], b1 = bias[c0 + 1];
                v0 += b0; v1 += b1; v2 += b0; v3 += b1;
            }
            if (BETA) {
                const float2 o0 = *(const float2*)p0;
                const float2 o1 = *(const float2*)p1;
                v0 += o0.x; v1 += o0.y; v2 += o1.x; v3 += o1.y;
            }
            *(float2*)p0 = make_float2(v0, v1);
            *(float2*)p1 = make_float2(v2, v3);
        }
    }
}

// ---------------------------------------------------------------------------
// LayerNorm: one block per token row (D = DM = 1024), 256 threads x float4.
// ---------------------------------------------------------------------------
__global__ void ln_kernel(const float* __restrict__ x, const float* __restrict__ w,
                          const float* __restrict__ b, float* __restrict__ o)
{
    __shared__ float s1[8], s2[8];
    const int row = blockIdx.x;
    const int tid = threadIdx.x;
    const float4 v = ((const float4*)(x + (size_t)row * DM))[tid];
    float s  = v.x + v.y + v.z + v.w;
    float ss = v.x * v.x + v.y * v.y + v.z * v.z + v.w * v.w;
#pragma unroll
    for (int off = 16; off; off >>= 1) {
        s  += __shfl_xor_sync(0xffffffffu, s,  off);
        ss += __shfl_xor_sync(0xffffffffu, ss, off);
    }
    if ((tid & 31) == 0) { s1[tid >> 5] = s; s2[tid >> 5] = ss; }
    __syncthreads();
    float ts = 0.f, tss = 0.f;
#pragma unroll
    for (int i = 0; i < 8; i++) { ts += s1[i]; tss += s2[i]; }
    const float mean = ts * (1.f / DM);
    const float var  = tss * (1.f / DM) - mean * mean;
    const float rstd = rsqrtf(var + 1e-5f);
    const float4 wv = ((const float4*)w)[tid];
    const float4 bv = ((const float4*)b)[tid];
    float4 r;
    r.x = (v.x - mean) * rstd * wv.x + bv.x;
    r.y = (v.y - mean) * rstd * wv.y + bv.y;
    r.z = (v.z - mean) * rstd * wv.z + bv.z;
    r.w = (v.w - mean) * rstd * wv.w + bv.w;
    ((float4*)(o + (size_t)row * DM))[tid] = r;
}

// ---------------------------------------------------------------------------
// Depthwise causal conv (K=4) + SiLU, reading xm-half of g_xz, writing g_xm.
// ---------------------------------------------------------------------------
__global__ void conv_kernel(const float* __restrict__ cw, const float* __restrict__ cb)
{
    const int idx = blockIdx.x * 256 + threadIdx.x;      // over Tt*EE
    const int e  = idx & (EE - 1);
    const int bt = idx >> 11;                            // b*Ll + t
    const int t  = bt & (Ll - 1);
    float acc = cb[e];
    const float* base = g_xz + (size_t)bt * (2 * EE) + e;
#pragma unroll
    for (int k = 0; k < 4; k++) {
        const int tt = t - 3 + k;
        if (tt >= 0) acc += cw[e * 4 + k] * base[(size_t)(k - 3) * (2 * EE)];
    }
    g_xm[idx] = acc / (1.f + __expf(-acc));
}

// ---------------------------------------------------------------------------
// dtproj GEMM + softplus: g_dt[T,2048] = softplus(xdbl[:, :64] * W[2048,64]^T + b)
// ---------------------------------------------------------------------------
__global__ __launch_bounds__(256)
void dt_kernel(const float* __restrict__ W, const float* __restrict__ db)
{
    __shared__ float Xs[16][64];
    __shared__ float Wt[64][132];
    const int tid = threadIdx.x;
    const int bm = blockIdx.y * 16;
    const int bn = blockIdx.x * 128;
    {
        const int m  = tid >> 4;
        const int k4 = (tid & 15) << 2;
        *(float4*)&Xs[m][k4] = *(const float4*)(g_xdbl + (size_t)(bm + m) * 96 + k4);
    }
#pragma unroll
    for (int r = 0; r < 8; r++) {
        const int idx = tid + 256 * r;
        const int n  = idx >> 4;
        const int k4 = (idx & 15) << 2;
        float4 v = *(const float4*)(W + (size_t)(bn + n) * 64 + k4);
        Wt[k4 + 0][n] = v.x; Wt[k4 + 1][n] = v.y;
        Wt[k4 + 2][n] = v.z; Wt[k4 + 3][n] = v.w;
    }
    __syncthreads();

    const int nb = (tid & 31) << 2;
    const int m0 = tid >> 5;
    float acc[2][4];
#pragma unroll
    for (int i = 0; i < 2; i++)
#pragma unroll
        for (int j = 0; j < 4; j++) acc[i][j] = 0.f;
#pragma unroll
    for (int k = 0; k < 64; k++) {
        const float4 w = *(const float4*)&Wt[k][nb];
        const float x0 = Xs[m0][k];
        const float x1 = Xs[m0 + 8][k];
        acc[0][0] = fmaf(x0, w.x, acc[0][0]); acc[0][1] = fmaf(x0, w.y, acc[0][1]);
        acc[0][2] = fmaf(x0, w.z, acc[0][2]); acc[0][3] = fmaf(x0, w.w, acc[0][3]);
        acc[1][0] = fmaf(x1, w.x, acc[1][0]); acc[1][1] = fmaf(x1, w.y, acc[1][1]);
        acc[1][2] = fmaf(x1, w.z, acc[1][2]); acc[1][3] = fmaf(x1, w.w, acc[1][3]);
    }
#pragma unroll
    for (int i = 0; i < 2; i++) {
        const int row = bm + m0 + 8 * i;
#pragma unroll
        for (int j = 0; j < 4; j++) {
            float v = acc[i][j] + db[bn + nb + j];
            v = (v > 20.f) ? v : log1pf(expf(v));
            g_dt[(size_t)row * EE + bn + nb + j] = v;
        }
    }
}

// ---------------------------------------------------------------------------
// Selective scan v2: chunked smem staging (CH timesteps, double-buffered
// cp.async) + x4-unrolled interleaved shfl reductions.
// Block = 128 threads = 8 channels (e) x 16 state lanes (n); grid (EE/8, Bb).
// y = (scan + u*D) * silu(zg) fused.
// ---------------------------------------------------------------------------
#define CH 64
__global__ __launch_bounds__(128)
void scan_kernel(int layer, const float* __restrict__ Dl)
{
    __shared__ float s_dt[2][CH][8];
    __shared__ float s_u [2][CH][8];
    __shared__ float s_zg[2][CH][8];
    __shared__ float s_B [2][CH][16];
    __shared__ float s_C [2][CH][16];
    __shared__ float s_y [CH][8];

    const int b   = blockIdx.y;
    const int e0  = blockIdx.x * 8;
    const int tid = threadIdx.x;
    const int eg  = tid >> 4;     // 0..7
    const int n   = tid & 15;

    const float Av = g_A[(size_t)layer * EE * NN + (e0 + eg) * NN + n];
    const float Dv = Dl[e0 + eg];

    auto load_chunk = [&](int buf, int t0) {
        const size_t bt0 = (size_t)(b * Ll + t0);
#pragma unroll
        for (int it = 0; it < 4; it++) {
            const int idx = tid + it * 128;
            const int t = idx >> 3, e = idx & 7;
            cp4(&s_dt[buf][t][e], &g_dt[(bt0 + t) * EE + e0 + e]);
            cp4(&s_u [buf][t][e], &g_xm[(bt0 + t) * EE + e0 + e]);
            cp4(&s_zg[buf][t][e], &g_xz[(bt0 + t) * (2 * EE) + EE + e0 + e]);
        }
#pragma unroll
        for (int it = 0; it < 8; it++) {
            const int idx = tid + it * 128;
            const int t = idx >> 4, nn = idx & 15;
            cp4(&s_B[buf][t][nn], &g_xdbl[(bt0 + t) * 96 + 64 + nn]);
            cp4(&s_C[buf][t][nn], &g_xdbl[(bt0 + t) * 96 + 80 + nn]);
        }
        cpcommit();
    };

    load_chunk(0, 0);

    float h = 0.f;
    const int NC = Ll / CH;
    for (int c = 0; c < NC; c++) {
        const int buf = c & 1;
        if (c + 1 < NC) { load_chunk(buf ^ 1, (c + 1) * CH); cpwait<1>(); }
        else            { cpwait<0>(); }
        __syncthreads();

#pragma unroll 4
        for (int tb = 0; tb < CH; tb += 4) {
            float p[4];
#pragma unroll
            for (int j = 0; j < 4; j++) {
                const float dt = s_dt[buf][tb + j][eg];
                const float uu = s_u [buf][tb + j][eg];
                const float Bv = s_B [buf][tb + j][n];
                const float Cv = s_C [buf][tb + j][n];
                const float dA = __expf(dt * Av);
                h = fmaf(dA, h, dt * uu * Bv);
                p[j] = h * Cv;
            }
#pragma unroll
            for (int off = 8; off; off >>= 1)
#pragma unroll
                for (int j = 0; j < 4; j++)
                    p[j] += __shfl_xor_sync(0xffffffffu, p[j], off);
            if (n == 0) {
#pragma unroll
                for (int j = 0; j < 4; j++) {
                    const float uu = s_u [buf][tb + j][eg];
                    const float zg = s_zg[buf][tb + j][eg];
                    const float sil = zg / (1.f + __expf(-zg));
                    s_y[tb + j][eg] = (p[j] + uu * Dv) * sil;
                }
            }
        }
        __syncthreads();

        // coalesced y store
        const size_t bt0 = (size_t)(b * Ll + c * CH);
#pragma unroll
        for (int it = 0; it < 4; it++) {
            const int idx = tid + it * 128;
            const int t = idx >> 3, e = idx & 7;
            g_y[(bt0 + t) * EE + e0 + e] = s_y[t][e];
        }
    }
}

// ---------------------------------------------------------------------------
__global__ void prep_A(const float* __restrict__ A_log)
{
    const int i = blockIdx.x * 256 + threadIdx.x;
    g_A[i] = -expf(A_log[i]);
}

// ---------------------------------------------------------------------------
extern "C" void kernel_launch(void* const* d_in, const int* in_sizes, int n_in,
                              void* d_out, int out_size)
{
    const float* x         = (const float*)d_in[0];
    const float* ip_w      = (const float*)d_in[2];
    const float* ip_b      = (const float*)d_in[3];
    const float* ln_w      = (const float*)d_in[4];
    const float* ln_b      = (const float*)d_in[5];
    const float* inproj_w  = (const float*)d_in[6];
    const float* conv_w    = (const float*)d_in[7];
    const float* conv_b    = (const float*)d_in[8];
    const float* xproj_w   = (const float*)d_in[9];
    const float* dtproj_w  = (const float*)d_in[10];
    const float* dtproj_b  = (const float*)d_in[11];
    const float* A_log     = (const float*)d_in[12];
    const float* Dp        = (const float*)d_in[13];
    const float* outproj_w = (const float*)d_in[14];
    const float* fnorm_w   = (const float*)d_in[15];
    const float* fnorm_b   = (const float*)d_in[16];
    const float* op_w      = (const float*)d_in[17];
    const float* op_b      = (const float*)d_in[18];
    float* out = (float*)d_out;

    float *p_h, *p_hn, *p_xz, *p_xm, *p_xdbl, *p_y;
    cudaGetSymbolAddress((void**)&p_h,    g_h);
    cudaGetSymbolAddress((void**)&p_hn,   g_hn);
    cudaGetSymbolAddress((void**)&p_xz,   g_xz);
    cudaGetSymbolAddress((void**)&p_xm,   g_xm);
    cudaGetSymbolAddress((void**)&p_xdbl, g_xdbl);
    cudaGetSymbolAddress((void**)&p_y,    g_y);

    prep_A<<<(NLr * EE * NN) / 256, 256>>>(A_log);

    // h = x @ ip_w^T + ip_b  (tf32)
    tgemm<2, 4, 0, 1><<<dim3(DM / 128, Tt / 128), 256>>>(x, ip_w, ip_b, p_h, Tt, DM, DIN);

    for (int l = 0; l < NLr; l++) {
        ln_kernel<<<Tt, 256>>>(p_h, ln_w + (size_t)l * DM, ln_b + (size_t)l * DM, p_hn);

        // xz = hn @ inproj_w^T   [T, 4096]
        tgemm<2, 4, 0, 0><<<dim3((2 * EE) / 128, Tt / 128), 256>>>(
            p_hn, inproj_w + (size_t)l * 2 * EE * DM, nullptr, p_xz, Tt, 2 * EE, DM);

        // xm = silu(causal depthwise conv)
        conv_kernel<<<(Tt * EE) / 256, 256>>>(conv_w + (size_t)l * EE * 4,
                                              conv_b + (size_t)l * EE);

        // x_dbl = xm @ xproj_w^T   [T, 96]
        tgemm<2, 3, 0, 0><<<dim3(1, Tt / 128), 192>>>(
            p_xm, xproj_w + (size_t)l * 96 * EE, nullptr, p_xdbl, Tt, 96, EE);

        // dt = softplus(x_dbl[:, :64] @ dtproj_w^T + b)   [T, 2048]
        dt_kernel<<<dim3(EE / 128, Tt / 16), 256>>>(dtproj_w + (size_t)l * EE * RR,
                                                    dtproj_b + (size_t)l * EE);

        // selective scan + gating  -> y [T, 2048]
        scan_kernel<<<dim3(EE / 8, Bb), 128>>>(l, Dp + (size_t)l * EE);

        // h += y @ outproj_w^T
        tgemm<2, 4, 1, 0><<<dim3(DM / 128, Tt / 128), 256>>>(
            p_y, outproj_w + (size_t)l * DM * EE, nullptr, p_h, Tt, DM, EE);
    }

    ln_kernel<<<Tt, 256>>>(p_h, fnorm_w, fnorm_b, p_hn);

    // out = hn @ op_w^T + op_b   [T, 512]
    tgemm<2, 4, 0, 1><<<dim3(DIN / 128, Tt / 128), 256>>>(p_hn, op_w, op_b, out, Tt, DIN, DM);
}

// round 5
// speedup vs baseline: 4.1556x; 1.2203x over previous
#include <cuda_runtime.h>
#include <math.h>
#include <stdint.h>

// Problem constants
#define Bb   2
#define Ll   1024
#define Tt   2048        // Bb*Ll tokens
#define DIN  512
#define DM   1024
#define NLr  4
#define EE   2048
#define NN   16
#define RR   64
#define XSK  8           // split-K factor for xproj

// ---------------- scratch (device globals; no runtime allocation) ----------
__device__ float g_h   [Tt * DM];
__device__ float g_hn  [Tt * DM];
__device__ float g_xz  [Tt * 2 * EE];
__device__ float g_xm  [Tt * EE];
__device__ float g_xdbl[Tt * 96];
__device__ float g_dt  [Tt * EE];
__device__ float g_y   [Tt * EE];
__device__ float g_A   [NLr * EE * NN];
__device__ float g_xr  [Tt * DIN];                 // tf32-rounded x
__device__ float g_xpart[XSK * Tt * 96];           // xproj split-K partials
// tf32-rounded weights
__device__ float g_wip     [DM * DIN];
__device__ float g_winproj [NLr * 2 * EE * DM];
__device__ float g_wxproj  [NLr * 96 * EE];
__device__ float g_woutproj[NLr * DM * EE];
__device__ float g_wop     [DIN * DM];

// ---------------------------------------------------------------------------
// helpers
// ---------------------------------------------------------------------------
__device__ __forceinline__ uint32_t f2tf(float x) {
    uint32_t r;
    asm("cvt.rna.tf32.f32 %0, %1;" : "=r"(r) : "f"(x));
    return r;
}
__device__ __forceinline__ float rtf(float x) { return __uint_as_float(f2tf(x)); }

__device__ __forceinline__ void mma8(float& d0, float& d1, float& d2, float& d3,
                                     uint32_t a0, uint32_t a1, uint32_t a2, uint32_t a3,
                                     uint32_t b0, uint32_t b1) {
    asm volatile(
        "mma.sync.aligned.m16n8k8.row.col.f32.tf32.tf32.f32 "
        "{%0,%1,%2,%3}, {%4,%5,%6,%7}, {%8,%9}, {%0,%1,%2,%3};"
        : "+f"(d0), "+f"(d1), "+f"(d2), "+f"(d3)
        : "r"(a0), "r"(a1), "r"(a2), "r"(a3), "r"(b0), "r"(b1));
}
__device__ __forceinline__ void ldsm4(uint32_t* r, uint32_t a) {
    asm volatile("ldmatrix.sync.aligned.m8n8.x4.shared.b16 {%0,%1,%2,%3}, [%4];"
                 : "=r"(r[0]), "=r"(r[1]), "=r"(r[2]), "=r"(r[3]) : "r"(a));
}
__device__ __forceinline__ void ldsm2(uint32_t* r, uint32_t a) {
    asm volatile("ldmatrix.sync.aligned.m8n8.x2.shared.b16 {%0,%1}, [%2];"
                 : "=r"(r[0]), "=r"(r[1]) : "r"(a));
}
__device__ __forceinline__ void cp16(void* dst, const void* src) {
    uint32_t d = (uint32_t)__cvta_generic_to_shared(dst);
    asm volatile("cp.async.cg.shared.global [%0], [%1], 16;" :: "r"(d), "l"(src));
}
__device__ __forceinline__ void cp4(void* dst, const void* src) {
    uint32_t d = (uint32_t)__cvta_generic_to_shared(dst);
    asm volatile("cp.async.ca.shared.global [%0], [%1], 4;" :: "r"(d), "l"(src));
}
__device__ __forceinline__ void cpcommit() { asm volatile("cp.async.commit_group;"); }
template<int NG> __device__ __forceinline__ void cpwait() {
    asm volatile("cp.async.wait_group %0;" :: "n"(NG));
}

// ---------------------------------------------------------------------------
// TF32 tensor GEMM v5: C[M,N] = A[M,K] * W[N,K]^T (+bias) (+= if BETA)
// Inputs MUST be pre-rounded to tf32. 3-stage cp.async, ldmatrix fragments,
// one __syncthreads per k-tile. lda = row stride of A and W (= total K).
// SK: split-K over blockIdx.z (chunk length = K), C -> partials [z][M][N].
// ---------------------------------------------------------------------------
template<int WMW, int WNW, int BETA, int BIAS, int SK>
__global__ __launch_bounds__(WMW * WNW * 32, 2)
void tgemm(const float* __restrict__ A, const float* __restrict__ W,
           const float* __restrict__ bias, float* __restrict__ C,
           int M, int N, int K, int lda)
{
    constexpr int NT  = WMW * WNW * 32;
    constexpr int BM  = WMW * 64;
    constexpr int BN  = WNW * 32;
    constexpr int ST  = 3;
    constexpr int AW  = BM * 20;      // words per A stage
    constexpr int BW  = BN * 20;      // words per B stage
    constexpr int AIT = (BM * 4 + NT - 1) / NT;   // 16B chunks per thread (A)
    constexpr int BIT = (BN * 4 + NT - 1) / NT;   // 16B chunks per thread (B)

    extern __shared__ float dynsm[];

    if (SK) {
        A += (size_t)blockIdx.z * K;
        W += (size_t)blockIdx.z * K;
        C += (size_t)blockIdx.z * M * N;
    }

    const int tid  = threadIdx.x;
    const int bm   = blockIdx.y * BM;
    const int bn   = blockIdx.x * BN;
    const int wid  = tid >> 5;
    const int lane = tid & 31;
    const int wm   = wid % WMW;
    const int wn   = wid / WMW;
    const int l4   = lane >> 2;
    const int lr   = lane & 3;

    const float* Ag = A + (size_t)bm * lda;
    const float* Wg = W + (size_t)bn * lda;

    float acc[4][4][4];
#pragma unroll
    for (int i = 0; i < 4; i++)
#pragma unroll
        for (int j = 0; j < 4; j++)
#pragma unroll
            for (int k = 0; k < 4; k++) acc[i][j][k] = 0.f;

    auto load_stage = [&](int st, int kt) {
        float* As = dynsm + st * AW;
        float* Bs = dynsm + ST * AW + st * BW;
#pragma unroll
        for (int i = 0; i < AIT; i++) {
            const int f = tid + i * NT;
            if (f < BM * 4) {
                const int row = f >> 2, c = (f & 3) << 2;
                cp16(As + row * 20 + c, Ag + (size_t)row * lda + kt * 16 + c);
            }
        }
#pragma unroll
        for (int i = 0; i < BIT; i++) {
            const int f = tid + i * NT;
            if (f < BN * 4) {
                const int row = f >> 2, c = (f & 3) << 2;
                cp16(Bs + row * 20 + c, Wg + (size_t)row * lda + kt * 16 + c);
            }
        }
        cpcommit();
    };

    load_stage(0, 0);
    load_stage(1, 1);

    // per-lane ldmatrix offsets (words)
    const int sub  = lane >> 3, tr = lane & 7;
    const int aoff = ((sub & 1) * 8 + tr) * 20 + (sub >> 1) * 4;
    const int l15  = lane & 15;
    const int boff = (l15 & 7) * 20 + (l15 >> 3) * 4;
    const uint32_t Au = (uint32_t)__cvta_generic_to_shared(dynsm);
    const uint32_t Bu = (uint32_t)__cvta_generic_to_shared(dynsm + ST * AW);

    const int nt = K >> 4;
    for (int kt = 0; kt < nt; kt++) {
        cpwait<1>();
        __syncthreads();
        if (kt + 2 < nt) load_stage((kt + 2) % ST, kt + 2);

        const int st = kt % ST;
        const uint32_t aB = Au + (uint32_t)(st * AW + wm * 64 * 20 + aoff) * 4;
        const uint32_t bB = Bu + (uint32_t)(st * BW + wn * 32 * 20 + boff) * 4;
#pragma unroll
        for (int ks = 0; ks < 2; ks++) {
            uint32_t af[4][4], bf[4][2];
#pragma unroll
            for (int mt = 0; mt < 4; mt++)
                ldsm4(af[mt], aB + (uint32_t)(mt * 16 * 20 + ks * 8) * 4);
#pragma unroll
            for (int ntt = 0; ntt < 4; ntt++)
                ldsm2(bf[ntt], bB + (uint32_t)(ntt * 8 * 20 + ks * 8) * 4);
#pragma unroll
            for (int mt = 0; mt < 4; mt++)
#pragma unroll
                for (int ntt = 0; ntt < 4; ntt++)
                    mma8(acc[mt][ntt][0], acc[mt][ntt][1], acc[mt][ntt][2], acc[mt][ntt][3],
                         af[mt][0], af[mt][1], af[mt][2], af[mt][3],
                         bf[ntt][0], bf[ntt][1]);
        }
    }

    // Epilogue (fp32)
#pragma unroll
    for (int mt = 0; mt < 4; mt++) {
        const int r0 = bm + wm * 64 + mt * 16 + l4;
#pragma unroll
        for (int ntt = 0; ntt < 4; ntt++) {
            const int c0 = bn + wn * 32 + ntt * 8 + lr * 2;
            float* p0 = C + (size_t)r0 * N + c0;
            float* p1 = p0 + (size_t)8 * N;
            float v0 = acc[mt][ntt][0], v1 = acc[mt][ntt][1];
            float v2 = acc[mt][ntt][2], v3 = acc[mt][ntt][3];
            if (BIAS) {
                const float b0 = bias[c0], b1 = bias[c0 + 1];
                v0 += b0; v1 += b1; v2 += b0; v3 += b1;
            }
            if (BETA) {
                const float2 o0 = *(const float2*)p0;
                const float2 o1 = *(const float2*)p1;
                v0 += o0.x; v1 += o0.y; v2 += o1.x; v3 += o1.y;
            }
            *(float2*)p0 = make_float2(v0, v1);
            *(float2*)p1 = make_float2(v2, v3);
        }
    }
}

// ---------------------------------------------------------------------------
// tf32 rounding prep (vectorized)
// ---------------------------------------------------------------------------
__global__ void round_tf32(const float4* __restrict__ s, float4* __restrict__ d, int n4)
{
    const int i = blockIdx.x * 256 + threadIdx.x;
    if (i < n4) {
        float4 v = s[i];
        v.x = rtf(v.x); v.y = rtf(v.y); v.z = rtf(v.z); v.w = rtf(v.w);
        d[i] = v;
    }
}

// ---------------------------------------------------------------------------
// xproj split-K reduction: xdbl = sum_z partials
// ---------------------------------------------------------------------------
__global__ void xred_kernel()
{
    const int i = blockIdx.x * 256 + threadIdx.x;   // Tt*96
    float s = 0.f;
#pragma unroll
    for (int z = 0; z < XSK; z++) s += g_xpart[(size_t)z * Tt * 96 + i];
    g_xdbl[i] = s;
}

// ---------------------------------------------------------------------------
// LayerNorm (output rounded to tf32 — feeds GEMMs only)
// ---------------------------------------------------------------------------
__global__ void ln_kernel(const float* __restrict__ x, const float* __restrict__ w,
                          const float* __restrict__ b, float* __restrict__ o)
{
    __shared__ float s1[8], s2[8];
    const int row = blockIdx.x;
    const int tid = threadIdx.x;
    const float4 v = ((const float4*)(x + (size_t)row * DM))[tid];
    float s  = v.x + v.y + v.z + v.w;
    float ss = v.x * v.x + v.y * v.y + v.z * v.z + v.w * v.w;
#pragma unroll
    for (int off = 16; off; off >>= 1) {
        s  += __shfl_xor_sync(0xffffffffu, s,  off);
        ss += __shfl_xor_sync(0xffffffffu, ss, off);
    }
    if ((tid & 31) == 0) { s1[tid >> 5] = s; s2[tid >> 5] = ss; }
    __syncthreads();
    float ts = 0.f, tss = 0.f;
#pragma unroll
    for (int i = 0; i < 8; i++) { ts += s1[i]; tss += s2[i]; }
    const float mean = ts * (1.f / DM);
    const float var  = tss * (1.f / DM) - mean * mean;
    const float rstd = rsqrtf(var + 1e-5f);
    const float4 wv = ((const float4*)w)[tid];
    const float4 bv = ((const float4*)b)[tid];
    float4 r;
    r.x = rtf((v.x - mean) * rstd * wv.x + bv.x);
    r.y = rtf((v.y - mean) * rstd * wv.y + bv.y);
    r.z = rtf((v.z - mean) * rstd * wv.z + bv.z);
    r.w = rtf((v.w - mean) * rstd * wv.w + bv.w);
    ((float4*)(o + (size_t)row * DM))[tid] = r;
}

// ---------------------------------------------------------------------------
// Depthwise causal conv (K=4) + SiLU (output rounded to tf32)
// ---------------------------------------------------------------------------
__global__ void conv_kernel(const float* __restrict__ cw, const float* __restrict__ cb)
{
    const int idx = blockIdx.x * 256 + threadIdx.x;
    const int e  = idx & (EE - 1);
    const int bt = idx >> 11;
    const int t  = bt & (Ll - 1);
    float acc = cb[e];
    const float* base = g_xz + (size_t)bt * (2 * EE) + e;
#pragma unroll
    for (int k = 0; k < 4; k++) {
        const int tt = t - 3 + k;
        if (tt >= 0) acc += cw[e * 4 + k] * base[(size_t)(k - 3) * (2 * EE)];
    }
    g_xm[idx] = rtf(acc / (1.f + __expf(-acc)));
}

// ---------------------------------------------------------------------------
// dtproj GEMM + softplus (fp32)
// ---------------------------------------------------------------------------
__global__ __launch_bounds__(256)
void dt_kernel(const float* __restrict__ W, const float* __restrict__ db)
{
    __shared__ float Xs[16][64];
    __shared__ float Wt[64][132];
    const int tid = threadIdx.x;
    const int bm = blockIdx.y * 16;
    const int bn = blockIdx.x * 128;
    {
        const int m  = tid >> 4;
        const int k4 = (tid & 15) << 2;
        *(float4*)&Xs[m][k4] = *(const float4*)(g_xdbl + (size_t)(bm + m) * 96 + k4);
    }
#pragma unroll
    for (int r = 0; r < 8; r++) {
        const int idx = tid + 256 * r;
        const int n  = idx >> 4;
        const int k4 = (idx & 15) << 2;
        float4 v = *(const float4*)(W + (size_t)(bn + n) * 64 + k4);
        Wt[k4 + 0][n] = v.x; Wt[k4 + 1][n] = v.y;
        Wt[k4 + 2][n] = v.z; Wt[k4 + 3][n] = v.w;
    }
    __syncthreads();

    const int nb = (tid & 31) << 2;
    const int m0 = tid >> 5;
    float acc[2][4];
#pragma unroll
    for (int i = 0; i < 2; i++)
#pragma unroll
        for (int j = 0; j < 4; j++) acc[i][j] = 0.f;
#pragma unroll
    for (int k = 0; k < 64; k++) {
        const float4 w = *(const float4*)&Wt[k][nb];
        const float x0 = Xs[m0][k];
        const float x1 = Xs[m0 + 8][k];
        acc[0][0] = fmaf(x0, w.x, acc[0][0]); acc[0][1] = fmaf(x0, w.y, acc[0][1]);
        acc[0][2] = fmaf(x0, w.z, acc[0][2]); acc[0][3] = fmaf(x0, w.w, acc[0][3]);
        acc[1][0] = fmaf(x1, w.x, acc[1][0]); acc[1][1] = fmaf(x1, w.y, acc[1][1]);
        acc[1][2] = fmaf(x1, w.z, acc[1][2]); acc[1][3] = fmaf(x1, w.w, acc[1][3]);
    }
#pragma unroll
    for (int i = 0; i < 2; i++) {
        const int row = bm + m0 + 8 * i;
#pragma unroll
        for (int j = 0; j < 4; j++) {
            float v = acc[i][j] + db[bn + nb + j];
            v = (v > 20.f) ? v : log1pf(expf(v));
            g_dt[(size_t)row * EE + bn + nb + j] = v;
        }
    }
}

// ---------------------------------------------------------------------------
// Selective scan: chunked smem staging + x4-unrolled shfl reductions.
// y rounded to tf32 (feeds outproj GEMM only).
// ---------------------------------------------------------------------------
#define CH 64
__global__ __launch_bounds__(128)
void scan_kernel(int layer, const float* __restrict__ Dl)
{
    __shared__ float s_dt[2][CH][8];
    __shared__ float s_u [2][CH][8];
    __shared__ float s_zg[2][CH][8];
    __shared__ float s_B [2][CH][16];
    __shared__ float s_C [2][CH][16];
    __shared__ float s_y [CH][8];

    const int b   = blockIdx.y;
    const int e0  = blockIdx.x * 8;
    const int tid = threadIdx.x;
    const int eg  = tid >> 4;
    const int n   = tid & 15;

    const float Av = g_A[(size_t)layer * EE * NN + (e0 + eg) * NN + n];
    const float Dv = Dl[e0 + eg];

    auto load_chunk = [&](int buf, int t0) {
        const size_t bt0 = (size_t)(b * Ll + t0);
#pragma unroll
        for (int it = 0; it < 4; it++) {
            const int idx = tid + it * 128;
            const int t = idx >> 3, e = idx & 7;
            cp4(&s_dt[buf][t][e], &g_dt[(bt0 + t) * EE + e0 + e]);
            cp4(&s_u [buf][t][e], &g_xm[(bt0 + t) * EE + e0 + e]);
            cp4(&s_zg[buf][t][e], &g_xz[(bt0 + t) * (2 * EE) + EE + e0 + e]);
        }
#pragma unroll
        for (int it = 0; it < 8; it++) {
            const int idx = tid + it * 128;
            const int t = idx >> 4, nn = idx & 15;
            cp4(&s_B[buf][t][nn], &g_xdbl[(bt0 + t) * 96 + 64 + nn]);
            cp4(&s_C[buf][t][nn], &g_xdbl[(bt0 + t) * 96 + 80 + nn]);
        }
        cpcommit();
    };

    load_chunk(0, 0);

    float h = 0.f;
    const int NC = Ll / CH;
    for (int c = 0; c < NC; c++) {
        const int buf = c & 1;
        if (c + 1 < NC) { load_chunk(buf ^ 1, (c + 1) * CH); cpwait<1>(); }
        else            { cpwait<0>(); }
        __syncthreads();

#pragma unroll 4
        for (int tb = 0; tb < CH; tb += 4) {
            float p[4];
#pragma unroll
            for (int j = 0; j < 4; j++) {
                const float dt = s_dt[buf][tb + j][eg];
                const float uu = s_u [buf][tb + j][eg];
                const float Bv = s_B [buf][tb + j][n];
                const float Cv = s_C [buf][tb + j][n];
                const float dA = __expf(dt * Av);
                h = fmaf(dA, h, dt * uu * Bv);
                p[j] = h * Cv;
            }
#pragma unroll
            for (int off = 8; off; off >>= 1)
#pragma unroll
                for (int j = 0; j < 4; j++)
                    p[j] += __shfl_xor_sync(0xffffffffu, p[j], off);
            if (n == 0) {
#pragma unroll
                for (int j = 0; j < 4; j++) {
                    const float uu = s_u [buf][tb + j][eg];
                    const float zg = s_zg[buf][tb + j][eg];
                    const float sil = zg / (1.f + __expf(-zg));
                    s_y[tb + j][eg] = (p[j] + uu * Dv) * sil;
                }
            }
        }
        __syncthreads();

        const size_t bt0 = (size_t)(b * Ll + c * CH);
#pragma unroll
        for (int it = 0; it < 4; it++) {
            const int idx = tid + it * 128;
            const int t = idx >> 3, e = idx & 7;
            g_y[(bt0 + t) * EE + e0 + e] = rtf(s_y[t][e]);
        }
    }
}

// ---------------------------------------------------------------------------
__global__ void prep_A(const float* __restrict__ A_log)
{
    const int i = blockIdx.x * 256 + threadIdx.x;
    g_A[i] = -expf(A_log[i]);
}

// ---------------------------------------------------------------------------
extern "C" void kernel_launch(void* const* d_in, const int* in_sizes, int n_in,
                              void* d_out, int out_size)
{
    const float* x         = (const float*)d_in[0];
    const float* ip_w      = (const float*)d_in[2];
    const float* ip_b      = (const float*)d_in[3];
    const float* ln_w      = (const float*)d_in[4];
    const float* ln_b      = (const float*)d_in[5];
    const float* inproj_w  = (const float*)d_in[6];
    const float* conv_w    = (const float*)d_in[7];
    const float* conv_b    = (const float*)d_in[8];
    const float* xproj_w   = (const float*)d_in[9];
    const float* dtproj_w  = (const float*)d_in[10];
    const float* dtproj_b  = (const float*)d_in[11];
    const float* A_log     = (const float*)d_in[12];
    const float* Dp        = (const float*)d_in[13];
    const float* outproj_w = (const float*)d_in[14];
    const float* fnorm_w   = (const float*)d_in[15];
    const float* fnorm_b   = (const float*)d_in[16];
    const float* op_w      = (const float*)d_in[17];
    const float* op_b      = (const float*)d_in[18];
    float* out = (float*)d_out;

    float *p_h, *p_hn, *p_xz, *p_xm, *p_y, *p_xr, *p_xpart;
    float *p_wip, *p_winproj, *p_wxproj, *p_woutproj, *p_wop;
    cudaGetSymbolAddress((void**)&p_h,        g_h);
    cudaGetSymbolAddress((void**)&p_hn,       g_hn);
    cudaGetSymbolAddress((void**)&p_xz,       g_xz);
    cudaGetSymbolAddress((void**)&p_xm,       g_xm);
    cudaGetSymbolAddress((void**)&p_y,        g_y);
    cudaGetSymbolAddress((void**)&p_xr,       g_xr);
    cudaGetSymbolAddress((void**)&p_xpart,    g_xpart);
    cudaGetSymbolAddress((void**)&p_wip,      g_wip);
    cudaGetSymbolAddress((void**)&p_winproj,  g_winproj);
    cudaGetSymbolAddress((void**)&p_wxproj,   g_wxproj);
    cudaGetSymbolAddress((void**)&p_woutproj, g_woutproj);
    cudaGetSymbolAddress((void**)&p_wop,      g_wop);

    // opt-in dynamic smem (61.4 KB / 53.8 KB per block)
    const int SM4 = 3 * (128 * 20 + 128 * 20) * 4;
    const int SM3 = 3 * (128 * 20 +  96 * 20) * 4;
    cudaFuncSetAttribute(tgemm<2,4,0,0,0>, cudaFuncAttributeMaxDynamicSharedMemorySize, SM4);
    cudaFuncSetAttribute(tgemm<2,4,0,1,0>, cudaFuncAttributeMaxDynamicSharedMemorySize, SM4);
    cudaFuncSetAttribute(tgemm<2,4,1,0,0>, cudaFuncAttributeMaxDynamicSharedMemorySize, SM4);
    cudaFuncSetAttribute(tgemm<2,3,0,0,1>, cudaFuncAttributeMaxDynamicSharedMemorySize, SM3);

    prep_A<<<(NLr * EE * NN) / 256, 256>>>(A_log);

    // tf32-round inputs/weights (numerically identical to in-GEMM cvt)
    auto rd = [](const float* s, float* d, size_t n) {
        round_tf32<<<(int)((n / 4 + 255) / 256), 256>>>((const float4*)s, (float4*)d, (int)(n / 4));
    };
    rd(x,         p_xr,       (size_t)Tt * DIN);
    rd(ip_w,      p_wip,      (size_t)DM * DIN);
    rd(inproj_w,  p_winproj,  (size_t)NLr * 2 * EE * DM);
    rd(xproj_w,   p_wxproj,   (size_t)NLr * 96 * EE);
    rd(outproj_w, p_woutproj, (size_t)NLr * DM * EE);
    rd(op_w,      p_wop,      (size_t)DIN * DM);

    // h = x @ ip_w^T + ip_b
    tgemm<2,4,0,1,0><<<dim3(DM / 128, Tt / 128), 256, SM4>>>(
        p_xr, p_wip, ip_b, p_h, Tt, DM, DIN, DIN);

    for (int l = 0; l < NLr; l++) {
        ln_kernel<<<Tt, 256>>>(p_h, ln_w + (size_t)l * DM, ln_b + (size_t)l * DM, p_hn);

        // xz = hn @ inproj_w^T   [T, 4096]
        tgemm<2,4,0,0,0><<<dim3((2 * EE) / 128, Tt / 128), 256, SM4>>>(
            p_hn, p_winproj + (size_t)l * 2 * EE * DM, nullptr, p_xz, Tt, 2 * EE, DM, DM);

        conv_kernel<<<(Tt * EE) / 256, 256>>>(conv_w + (size_t)l * EE * 4,
                                              conv_b + (size_t)l * EE);

        // x_dbl = xm @ xproj_w^T   [T, 96]  split-K over 8 chunks of 256
        tgemm<2,3,0,0,1><<<dim3(1, Tt / 128, XSK), 192, SM3>>>(
            p_xm, p_wxproj + (size_t)l * 96 * EE, nullptr, p_xpart,
            Tt, 96, EE / XSK, EE);
        xred_kernel<<<(Tt * 96) / 256, 256>>>();

        dt_kernel<<<dim3(EE / 128, Tt / 16), 256>>>(dtproj_w + (size_t)l * EE * RR,
                                                    dtproj_b + (size_t)l * EE);

        scan_kernel<<<dim3(EE / 8, Bb), 128>>>(l, Dp + (size_t)l * EE);

        // h += y @ outproj_w^T
        tgemm<2,4,1,0,0><<<dim3(DM / 128, Tt / 128), 256, SM4>>>(
            p_y, p_woutproj + (size_t)l * DM * EE, nullptr, p_h, Tt, DM, EE, EE);
    }

    ln_kernel<<<Tt, 256>>>(p_h, fnorm_w, fnorm_b, p_hn);

    // out = hn @ op_w^T + op_b   [T, 512]
    tgemm<2,4,0,1,0><<<dim3(DIN / 128, Tt / 128), 256, SM4>>>(
        p_hn, p_wop, op_b, out, Tt, DIN, DM, DM);
}